// round 1
// baseline (speedup 1.0000x reference)
#include <cuda_runtime.h>
#include <math.h>

// Problem constants
#define NB 4
#define NS 2048
#define ND 1024
#define NHALF 512
#define NBS (NB*NS)            // 8192
#define NBSD (NB*NS*ND)        // 8388608
#define NBSS (NB*NS*NS)        // 16777216

// ---------------- scratch (static device globals; no allocation) -------------
__device__ float g_Q[NBSD];
__device__ float g_Kb[NBSD];
__device__ float g_V[NBSD];
__device__ float g_P[NBSD];     // phase pre-activation scratch
__device__ float g_CSq[NBSD];   // [cos | sin] of pQ, concatenated along feature dim
__device__ float g_CSk[NBSD];
__device__ float g_Sc[NBSS];    // scores -> attn (overwritten in place)
__device__ float g_Sy[NBSS];    // sync
__device__ float g_AV[NBSD];
__device__ float g_rowvar[NBS]; // per-row variance of sync (deterministic reduce)

// ---------------- GEMM NT: C[m,n] = alpha * sum_k A[m,k]*B[n,k] (+bias[n]) ----
// Tiles: 64x64 output per block, TK=32, 256 threads, 4x4 per thread.
#define TM 64
#define TN 64
#define TKK 32
#define SPAD 68

__global__ __launch_bounds__(256) void gemm_nt_kernel(
    const float* __restrict__ A, const float* __restrict__ Bm,
    const float* __restrict__ bias, float* __restrict__ C,
    int N, int Kd, float alpha,
    long long sA, long long sB, long long sC)
{
    __shared__ float As[TKK][SPAD];
    __shared__ float Bs[TKK][SPAD];

    const int bz = blockIdx.z;
    A  += (long long)bz * sA;
    Bm += (long long)bz * sB;
    C  += (long long)bz * sC;

    const int m0 = blockIdx.y * TM;
    const int n0 = blockIdx.x * TN;
    const int tid = threadIdx.x;
    const int tx = tid & 15;
    const int ty = tid >> 4;

    float acc[4][4] = {};

    for (int k0 = 0; k0 < Kd; k0 += TKK) {
        // Load A tile (64 rows x 32 k) and B tile (64 rows x 32 k), both NT
        #pragma unroll
        for (int it = 0; it < 2; it++) {
            int idx = tid + it * 256;         // 0..511
            int r   = idx >> 3;               // 0..63
            int c4  = idx & 7;                // 0..7
            float4 va = *(const float4*)&A [(long long)(m0 + r) * Kd + k0 + c4 * 4];
            As[c4*4+0][r] = va.x; As[c4*4+1][r] = va.y;
            As[c4*4+2][r] = va.z; As[c4*4+3][r] = va.w;
            float4 vb = *(const float4*)&Bm[(long long)(n0 + r) * Kd + k0 + c4 * 4];
            Bs[c4*4+0][r] = vb.x; Bs[c4*4+1][r] = vb.y;
            Bs[c4*4+2][r] = vb.z; Bs[c4*4+3][r] = vb.w;
        }
        __syncthreads();

        #pragma unroll
        for (int kk = 0; kk < TKK; kk++) {
            float4 a4 = *(const float4*)&As[kk][ty * 4];
            float4 b4 = *(const float4*)&Bs[kk][tx * 4];
            float a[4] = {a4.x, a4.y, a4.z, a4.w};
            float b[4] = {b4.x, b4.y, b4.z, b4.w};
            #pragma unroll
            for (int i = 0; i < 4; i++)
                #pragma unroll
                for (int j = 0; j < 4; j++)
                    acc[i][j] += a[i] * b[j];
        }
        __syncthreads();
    }

    #pragma unroll
    for (int i = 0; i < 4; i++) {
        int m = m0 + ty * 4 + i;
        #pragma unroll
        for (int j = 0; j < 4; j++) {
            int n = n0 + tx * 4 + j;
            float v = alpha * acc[i][j];
            if (bias) v += bias[n];
            C[(long long)m * N + n] = v;
        }
    }
}

// ---------------- GEMM NN: C[m,n] = sum_k A[m,k]*B[k,n] --------------------
__global__ __launch_bounds__(256) void gemm_nn_kernel(
    const float* __restrict__ A, const float* __restrict__ Bm,
    float* __restrict__ C,
    int N, int Kd,
    long long sA, long long sB, long long sC)
{
    __shared__ float As[TKK][SPAD];
    __shared__ float Bs[TKK][SPAD];

    const int bz = blockIdx.z;
    A  += (long long)bz * sA;
    Bm += (long long)bz * sB;
    C  += (long long)bz * sC;

    const int m0 = blockIdx.y * TM;
    const int n0 = blockIdx.x * TN;
    const int tid = threadIdx.x;
    const int tx = tid & 15;
    const int ty = tid >> 4;

    float acc[4][4] = {};

    for (int k0 = 0; k0 < Kd; k0 += TKK) {
        #pragma unroll
        for (int it = 0; it < 2; it++) {
            int idx = tid + it * 256;
            // A tile: transposed scatter (same as NT)
            int r  = idx >> 3;
            int c4 = idx & 7;
            float4 va = *(const float4*)&A[(long long)(m0 + r) * Kd + k0 + c4 * 4];
            As[c4*4+0][r] = va.x; As[c4*4+1][r] = va.y;
            As[c4*4+2][r] = va.z; As[c4*4+3][r] = va.w;
            // B tile: direct (row = k, cols contiguous)
            int rb  = idx >> 4;               // 0..31
            int cb4 = idx & 15;               // 0..15
            float4 vb = *(const float4*)&Bm[(long long)(k0 + rb) * N + n0 + cb4 * 4];
            *(float4*)&Bs[rb][cb4 * 4] = vb;
        }
        __syncthreads();

        #pragma unroll
        for (int kk = 0; kk < TKK; kk++) {
            float4 a4 = *(const float4*)&As[kk][ty * 4];
            float4 b4 = *(const float4*)&Bs[kk][tx * 4];
            float a[4] = {a4.x, a4.y, a4.z, a4.w};
            float b[4] = {b4.x, b4.y, b4.z, b4.w};
            #pragma unroll
            for (int i = 0; i < 4; i++)
                #pragma unroll
                for (int j = 0; j < 4; j++)
                    acc[i][j] += a[i] * b[j];
        }
        __syncthreads();
    }

    #pragma unroll
    for (int i = 0; i < 4; i++) {
        int m = m0 + ty * 4 + i;
        #pragma unroll
        for (int j = 0; j < 4; j++) {
            int n = n0 + tx * 4 + j;
            C[(long long)m * N + n] = acc[i][j];
        }
    }
}

// ---------------- phase: cos/sin of atan2 without trig ----------------------
__global__ void phase_kernel(const float* __restrict__ P, float* __restrict__ CS)
{
    int i = blockIdx.x * blockDim.x + threadIdx.x;
    if (i >= NBS * NHALF) return;
    int m = i / NHALF;
    int j = i - m * NHALF;
    float re = P[(long long)m * ND + j];
    float im = P[(long long)m * ND + j + NHALF];
    float r2 = re * re + im * im;
    float c, s;
    if (r2 > 0.0f) {
        float inv = rsqrtf(r2);
        c = re * inv; s = im * inv;
    } else { c = 1.0f; s = 0.0f; }   // atan2(0,0)=0
    CS[(long long)m * ND + j]         = c;
    CS[(long long)m * ND + j + NHALF] = s;
}

// ---------------- fused chaotic + softmax + sync-variance -------------------
__device__ __forceinline__ float block_reduce_max(float v, float* red) {
    int tid = threadIdx.x;
    red[tid] = v; __syncthreads();
    for (int s = 128; s > 0; s >>= 1) {
        if (tid < s) red[tid] = fmaxf(red[tid], red[tid + s]);
        __syncthreads();
    }
    float r = red[0]; __syncthreads();
    return r;
}
__device__ __forceinline__ float block_reduce_sum(float v, float* red) {
    int tid = threadIdx.x;
    red[tid] = v; __syncthreads();
    for (int s = 128; s > 0; s >>= 1) {
        if (tid < s) red[tid] += red[tid + s];
        __syncthreads();
    }
    float r = red[0]; __syncthreads();
    return r;
}

__global__ __launch_bounds__(256) void softmax_kernel(
    const float* __restrict__ bif_p, const float* __restrict__ pc_p)
{
    __shared__ float red[256];
    const int row = blockIdx.x;             // 0..NBS-1
    const float bif = *bif_p;
    const float pc  = *pc_p;
    float* sc       = g_Sc + (long long)row * NS;
    const float* sy = g_Sy + (long long)row * NS;

    float c[8];
    float lmax = -1e30f, lsy = 0.0f, lsy2 = 0.0f;
    #pragma unroll
    for (int j = 0; j < 8; j++) {
        int col = threadIdx.x + j * 256;
        float s = sc[col];
        float y = sy[col];
        float t = tanhf(s);
        float v = s + pc * y + bif * t * (1.0f - t);
        c[j] = v;
        lmax = fmaxf(lmax, v);
        lsy  += y;
        lsy2 += y * y;
    }
    float rmax = block_reduce_max(lmax, red);

    float lsum = 0.0f;
    #pragma unroll
    for (int j = 0; j < 8; j++) {
        c[j] = expf(c[j] - rmax);
        lsum += c[j];
    }
    float rsum = block_reduce_sum(lsum, red);
    float inv = 1.0f / rsum;
    #pragma unroll
    for (int j = 0; j < 8; j++) {
        int col = threadIdx.x + j * 256;
        sc[col] = c[j] * inv;
    }

    float tsy  = block_reduce_sum(lsy,  red);
    float tsy2 = block_reduce_sum(lsy2, red);
    if (threadIdx.x == 0) {
        float var = (tsy2 - tsy * tsy / (float)NS) / (float)(NS - 1);
        g_rowvar[row] = var;
    }
}

__global__ void finalize_kernel(float* __restrict__ out_scalar)
{
    __shared__ float red[256];
    float s = 0.0f;
    for (int i = threadIdx.x; i < NBS; i += 256) s += g_rowvar[i];
    float tot = block_reduce_sum(s, red);
    if (threadIdx.x == 0)
        *out_scalar = 0.01f * tot / (float)NBS;
}

// ---------------- launch ----------------------------------------------------
extern "C" void kernel_launch(void* const* d_in, const int* in_sizes, int n_in,
                              void* d_out, int out_size)
{
    const float* x   = (const float*)d_in[0];
    const float* Wq  = (const float*)d_in[1];
    const float* bq  = (const float*)d_in[2];
    const float* Wk  = (const float*)d_in[3];
    const float* bk  = (const float*)d_in[4];
    const float* Wv  = (const float*)d_in[5];
    const float* bv  = (const float*)d_in[6];
    const float* Wp  = (const float*)d_in[7];
    const float* bp  = (const float*)d_in[8];
    const float* Wo  = (const float*)d_in[9];
    const float* bo  = (const float*)d_in[10];
    const float* bif = (const float*)d_in[11];
    const float* pc  = (const float*)d_in[12];
    float* out = (float*)d_out;

    float *pQ, *pK, *pV, *pP, *pCSq, *pCSk, *pSc, *pSy, *pAV;
    cudaGetSymbolAddress((void**)&pQ,   g_Q);
    cudaGetSymbolAddress((void**)&pK,   g_Kb);
    cudaGetSymbolAddress((void**)&pV,   g_V);
    cudaGetSymbolAddress((void**)&pP,   g_P);
    cudaGetSymbolAddress((void**)&pCSq, g_CSq);
    cudaGetSymbolAddress((void**)&pCSk, g_CSk);
    cudaGetSymbolAddress((void**)&pSc,  g_Sc);
    cudaGetSymbolAddress((void**)&pSy,  g_Sy);
    cudaGetSymbolAddress((void**)&pAV,  g_AV);

    const float inv_sqrt_hd = 1.0f / 32.0f;     // 1/sqrt(1024)
    const float inv_half    = 1.0f / 512.0f;

    dim3 gp(ND / TN, NBS / TM, 1);              // (16,128,1) projections
    dim3 gs(NS / TN, NS / TM, NB);              // (32,32,4) score/sync
    dim3 ga(ND / TN, NS / TM, NB);              // (16,32,4) attn@V

    // Projections
    gemm_nt_kernel<<<gp, 256>>>(x, Wq, bq, pQ, ND, ND, 1.0f, 0, 0, 0);
    gemm_nt_kernel<<<gp, 256>>>(x, Wk, bk, pK, ND, ND, 1.0f, 0, 0, 0);
    gemm_nt_kernel<<<gp, 256>>>(x, Wv, bv, pV, ND, ND, 1.0f, 0, 0, 0);

    // Phase features
    int pn = NBS * NHALF;
    gemm_nt_kernel<<<gp, 256>>>(pQ, Wp, bp, pP, ND, ND, 1.0f, 0, 0, 0);
    phase_kernel<<<(pn + 255) / 256, 256>>>(pP, pCSq);
    gemm_nt_kernel<<<gp, 256>>>(pK, Wp, bp, pP, ND, ND, 1.0f, 0, 0, 0);
    phase_kernel<<<(pn + 255) / 256, 256>>>(pP, pCSk);

    // scores = Q K^T / sqrt(HD) ; sync = CSq CSk^T / HALF  (batched over NB)
    long long sQK = (long long)NS * ND;
    long long sSS = (long long)NS * NS;
    gemm_nt_kernel<<<gs, 256>>>(pQ,   pK,   nullptr, pSc, NS, ND, inv_sqrt_hd, sQK, sQK, sSS);
    gemm_nt_kernel<<<gs, 256>>>(pCSq, pCSk, nullptr, pSy, NS, ND, inv_half,    sQK, sQK, sSS);

    // chaotic + softmax (attn written in place into g_Sc) + per-row sync var
    softmax_kernel<<<NBS, 256>>>(bif, pc);

    // av = attn @ V   (NN, K = NS = 2048)
    gemm_nn_kernel<<<ga, 256>>>(pSc, pV, pAV, ND, NS, sSS, sQK, sQK);

    // out = av @ Wo^T + bo   -> straight into d_out
    gemm_nt_kernel<<<gp, 256>>>(pAV, Wo, bo, out, ND, ND, 1.0f, 0, 0, 0);

    // sync_loss scalar -> last element of output
    finalize_kernel<<<1, 256>>>(out + (out_size - 1));
}

// round 4
// speedup vs baseline: 4.0053x; 4.0053x over previous
#include <cuda_runtime.h>
#include <cuda_bf16.h>
#include <math.h>
#include <stdint.h>

// Problem constants
#define NB 4
#define NS 2048
#define ND 1024
#define NHALF 512
#define NBS (NB*NS)            // 8192
#define NBSD (NB*NS*ND)        // 8388608
#define NSS 16777216           // NB*NS*NS

// ---------------- scratch (static device globals; no allocation) -------------
__device__ float g_Q[NBSD];
__device__ float g_K[NBSD];
__device__ float g_V[NBSD];
__device__ float g_P[NBSD];
__device__ float g_Sc[NSS];     // scores fp32
__device__ float g_Sy[NSS];     // sync fp32
__device__ float g_AV[NBSD];
__device__ float g_rowvar[NBS];

__device__ __nv_bfloat16 g_xh[NBSD],  g_xl[NBSD];
__device__ __nv_bfloat16 g_Wqh[ND*ND], g_Wql[ND*ND];
__device__ __nv_bfloat16 g_Wkh[ND*ND], g_Wkl[ND*ND];
__device__ __nv_bfloat16 g_Wvh[ND*ND], g_Wvl[ND*ND];
__device__ __nv_bfloat16 g_Woh[ND*ND], g_Wol[ND*ND];
__device__ __nv_bfloat16 g_Wph[ND*ND];
__device__ __nv_bfloat16 g_Qh[NBSD], g_Ql[NBSD];
__device__ __nv_bfloat16 g_Kh[NBSD], g_Kl[NBSD];
__device__ __nv_bfloat16 g_Vth[NBSD], g_Vtl[NBSD];
__device__ __nv_bfloat16 g_CSqh[NBSD], g_CSkh[NBSD];
__device__ __nv_bfloat16 g_Ath[NSS], g_Atl[NSS];
__device__ __nv_bfloat16 g_AVh[NBSD], g_AVl[NBSD];

// ======================= PTX helpers (all sm_80-baseline) =======================
__device__ __forceinline__ uint32_t s2u(const void* p) {
    uint32_t a;
    asm("{ .reg .u64 t; cvta.to.shared.u64 t, %1; cvt.u32.u64 %0, t; }" : "=r"(a) : "l"(p));
    return a;
}
__device__ __forceinline__ void cp16(uint32_t dst, const void* src) {
    asm volatile("cp.async.cg.shared.global [%0], [%1], 16;" :: "r"(dst), "l"(src) : "memory");
}
__device__ __forceinline__ void cp_commit() {
    asm volatile("cp.async.commit_group;" ::: "memory");
}
__device__ __forceinline__ void cp_wait1() {
    asm volatile("cp.async.wait_group 1;" ::: "memory");
}
__device__ __forceinline__ void ldsm4(uint32_t& r0, uint32_t& r1, uint32_t& r2, uint32_t& r3,
                                      uint32_t addr) {
    asm volatile("ldmatrix.sync.aligned.m8n8.x4.shared.b16 {%0,%1,%2,%3}, [%4];"
                 : "=r"(r0), "=r"(r1), "=r"(r2), "=r"(r3) : "r"(addr));
}
__device__ __forceinline__ void mma16816(float* c, const uint32_t* a, const uint32_t* b) {
    asm volatile(
        "mma.sync.aligned.m16n8k16.row.col.f32.bf16.bf16.f32 "
        "{%0,%1,%2,%3}, {%4,%5,%6,%7}, {%8,%9}, {%0,%1,%2,%3};"
        : "+f"(c[0]), "+f"(c[1]), "+f"(c[2]), "+f"(c[3])
        : "r"(a[0]), "r"(a[1]), "r"(a[2]), "r"(a[3]), "r"(b[0]), "r"(b[1]));
}

// ======================= mma.sync GEMM NT =======================
// C[m,n] = alpha * sum_k (Ah+Al)[m,k]*(Bh+Bl)[n,k] (+bias[n])
// CTA tile M=128, N=256, K-chunk=64 (128B SW128 rows). 8 warps: 2(m) x 4(n),
// warp tile 64x64. 2-stage cp.async pipeline.
#define BM 128
#define BN 256
#define TA 16384    // 128 rows * 128B
#define TB 32768    // 256 rows * 128B

__device__ __forceinline__ void ld_tile(uint32_t dst, const __nv_bfloat16* g,
                                        int ldk, int rows, int tid) {
    const char* base = (const char*)g;
    int tot = rows * 8;
    for (int idx = tid; idx < tot; idx += 256) {
        int r = idx >> 3, c = idx & 7;
        uint32_t off = (uint32_t)(r * 128 + c * 16);
        uint32_t sw = off ^ ((off >> 3) & 0x70);
        cp16(dst + sw, base + (long long)r * ldk * 2 + c * 16);
    }
}

template<int SPLIT>
__device__ __forceinline__ void load_chunk(uint32_t sbase, int s,
    const __nv_bfloat16* pAh, const __nv_bfloat16* pAl,
    const __nv_bfloat16* pBh, const __nv_bfloat16* pBl,
    int Kd, int k0, int tid)
{
    const int STG = SPLIT ? (2 * TA + 2 * TB) : (TA + TB);
    uint32_t sb = sbase + s * STG;
    ld_tile(sb, pAh + k0, Kd, BM, tid);
    if (SPLIT) ld_tile(sb + TA, pAl + k0, Kd, BM, tid);
    ld_tile(sb + (SPLIT ? 2 * TA : TA), pBh + k0, Kd, BN, tid);
    if (SPLIT) ld_tile(sb + 2 * TA + TB, pBl + k0, Kd, BN, tid);
}

template<int SPLIT>
__global__ __launch_bounds__(256, 1)
void mma_gemm_nt(const __nv_bfloat16* __restrict__ Ah, const __nv_bfloat16* __restrict__ Al,
                 const __nv_bfloat16* __restrict__ Bh, const __nv_bfloat16* __restrict__ Bl,
                 const float* __restrict__ bias, float* __restrict__ C,
                 int N, int Kd, float alpha,
                 long long sA, long long sB, long long sC)
{
    extern __shared__ __align__(128) char smem[];
    const int STG = SPLIT ? (2 * TA + 2 * TB) : (TA + TB);
    const int tid = threadIdx.x;
    const int wid = tid >> 5, lane = tid & 31;
    const int wm = wid >> 2, wn = wid & 3;
    const uint32_t sbase = s2u(smem);

    const int m0 = blockIdx.y * BM, n0 = blockIdx.x * BN;
    const long long bz = blockIdx.z;
    const __nv_bfloat16* pAh = Ah + bz * sA + (long long)m0 * Kd;
    const __nv_bfloat16* pBh = Bh + bz * sB + (long long)n0 * Kd;
    const __nv_bfloat16* pAl = SPLIT ? Al + bz * sA + (long long)m0 * Kd : (const __nv_bfloat16*)0;
    const __nv_bfloat16* pBl = SPLIT ? Bl + bz * sB + (long long)n0 * Kd : (const __nv_bfloat16*)0;

    // per-lane swizzled base offsets for ldmatrix.
    // NOTE: k-advance within a chunk must be XORed (not added): the k-offset
    // bits (4..6) live inside the SW128 XOR field, and adding after the XOR
    // carries into the row bits (and off the end of smem for the last tile).
    const int qa = lane >> 3, rl = lane & 7;
    const int rowA = wm * 64 + (qa & 1) * 8 + rl;
    uint32_t offA = (uint32_t)(rowA * 128 + (qa >> 1) * 16);
    const uint32_t swA = offA ^ ((offA >> 3) & 0x70);
    const int rowB = wn * 64 + (qa >> 1) * 8 + rl;
    uint32_t offB = (uint32_t)(rowB * 128 + (qa & 1) * 16);
    const uint32_t swB = offB ^ ((offB >> 3) & 0x70);

    float acc[4][8][4];
    #pragma unroll
    for (int i = 0; i < 4; i++)
        #pragma unroll
        for (int j = 0; j < 8; j++)
            #pragma unroll
            for (int r = 0; r < 4; r++) acc[i][j][r] = 0.0f;

    const int nk = Kd / 64;
    load_chunk<SPLIT>(sbase, 0, pAh, pAl, pBh, pBl, Kd, 0, tid);  cp_commit();
    load_chunk<SPLIT>(sbase, 1, pAh, pAl, pBh, pBl, Kd, 64, tid); cp_commit();

    for (int i = 0; i < nk; i++) {
        int s = i & 1;
        cp_wait1();
        __syncthreads();

        uint32_t sb = sbase + s * STG;
        uint32_t aH = sb;
        uint32_t aL = sb + TA;
        uint32_t bH = sb + (SPLIT ? 2 * TA : TA);
        uint32_t bL = bH + TB;

        #pragma unroll
        for (int ks = 0; ks < 4; ks++) {
            uint32_t kb = ks * 32;
            uint32_t ah[4][4], bh[8][2];
            #pragma unroll
            for (int mt = 0; mt < 4; mt++)
                ldsm4(ah[mt][0], ah[mt][1], ah[mt][2], ah[mt][3],
                      aH + ((swA ^ kb) + mt * 2048));
            #pragma unroll
            for (int g = 0; g < 4; g++)
                ldsm4(bh[2*g][0], bh[2*g][1], bh[2*g+1][0], bh[2*g+1][1],
                      bH + ((swB ^ kb) + g * 2048));
            if (SPLIT) {
                uint32_t bl[8][2];
                #pragma unroll
                for (int g = 0; g < 4; g++)
                    ldsm4(bl[2*g][0], bl[2*g][1], bl[2*g+1][0], bl[2*g+1][1],
                          bL + ((swB ^ kb) + g * 2048));
                #pragma unroll
                for (int mt = 0; mt < 4; mt++)
                    #pragma unroll
                    for (int nt = 0; nt < 8; nt++) {
                        mma16816(acc[mt][nt], ah[mt], bh[nt]);
                        mma16816(acc[mt][nt], ah[mt], bl[nt]);
                    }
                uint32_t al[4][4];
                #pragma unroll
                for (int mt = 0; mt < 4; mt++)
                    ldsm4(al[mt][0], al[mt][1], al[mt][2], al[mt][3],
                          aL + ((swA ^ kb) + mt * 2048));
                #pragma unroll
                for (int mt = 0; mt < 4; mt++)
                    #pragma unroll
                    for (int nt = 0; nt < 8; nt++)
                        mma16816(acc[mt][nt], al[mt], bh[nt]);
            } else {
                #pragma unroll
                for (int mt = 0; mt < 4; mt++)
                    #pragma unroll
                    for (int nt = 0; nt < 8; nt++)
                        mma16816(acc[mt][nt], ah[mt], bh[nt]);
            }
        }

        __syncthreads();
        if (i + 2 < nk)
            load_chunk<SPLIT>(sbase, s, pAh, pAl, pBh, pBl, Kd, (i + 2) * 64, tid);
        cp_commit();
    }

    // epilogue
    float* pC = C + bz * sC;
    const int t4 = lane >> 2, t2 = (lane & 3) * 2;
    #pragma unroll
    for (int mt = 0; mt < 4; mt++) {
        int r0 = m0 + wm * 64 + mt * 16 + t4;
        #pragma unroll
        for (int nt = 0; nt < 8; nt++) {
            int col = n0 + wn * 64 + nt * 8 + t2;
            float b0 = 0.0f, b1 = 0.0f;
            if (bias) { b0 = bias[col]; b1 = bias[col + 1]; }
            float2 v0 = { alpha * acc[mt][nt][0] + b0, alpha * acc[mt][nt][1] + b1 };
            float2 v1 = { alpha * acc[mt][nt][2] + b0, alpha * acc[mt][nt][3] + b1 };
            *(float2*)&pC[(long long)r0 * N + col]       = v0;
            *(float2*)&pC[(long long)(r0 + 8) * N + col] = v1;
        }
    }
}

// ======================= elementwise kernels =======================
__global__ void split_kernel(const float* __restrict__ in,
                             __nv_bfloat16* __restrict__ h, __nv_bfloat16* __restrict__ l, int n)
{
    int i = blockIdx.x * blockDim.x + threadIdx.x;
    if (i >= n) return;
    float f = in[i];
    __nv_bfloat16 hb = __float2bfloat16(f);
    h[i] = hb;
    l[i] = __float2bfloat16(f - __bfloat162float(hb));
}

__global__ void conv_kernel(const float* __restrict__ in, __nv_bfloat16* __restrict__ h, int n)
{
    int i = blockIdx.x * blockDim.x + threadIdx.x;
    if (i >= n) return;
    h[i] = __float2bfloat16(in[i]);
}

// transpose V[b][s][d] -> Vt[b][d][s], split into bf16 hi/lo
__global__ void transpose_split_kernel(const float* __restrict__ V,
                                       __nv_bfloat16* __restrict__ Th, __nv_bfloat16* __restrict__ Tl)
{
    __shared__ float t[32][33];
    int b = blockIdx.z;
    int s0 = blockIdx.x * 32, d0 = blockIdx.y * 32;
    int tx = threadIdx.x, ty = threadIdx.y;
    #pragma unroll
    for (int yy = 0; yy < 4; yy++) {
        int s = s0 + ty + 8 * yy;
        t[ty + 8 * yy][tx] = V[((long long)b * NS + s) * ND + d0 + tx];
    }
    __syncthreads();
    #pragma unroll
    for (int yy = 0; yy < 4; yy++) {
        int d = d0 + ty + 8 * yy;
        int s = s0 + tx;
        float f = t[tx][ty + 8 * yy];
        __nv_bfloat16 hb = __float2bfloat16(f);
        long long o = ((long long)b * ND + d) * NS + s;
        Th[o] = hb;
        Tl[o] = __float2bfloat16(f - __bfloat162float(hb));
    }
}

// phase features: cos/sin of atan2 -> bf16 [cos | sin]
__global__ void phase_kernel(const float* __restrict__ P, __nv_bfloat16* __restrict__ CS)
{
    int i = blockIdx.x * blockDim.x + threadIdx.x;
    if (i >= NBS * NHALF) return;
    int m = i / NHALF;
    int j = i - m * NHALF;
    float re = P[(long long)m * ND + j];
    float im = P[(long long)m * ND + j + NHALF];
    float r2 = re * re + im * im;
    float c, s;
    if (r2 > 0.0f) {
        float inv = rsqrtf(r2);
        c = re * inv; s = im * inv;
    } else { c = 1.0f; s = 0.0f; }
    CS[(long long)m * ND + j]         = __float2bfloat16(c);
    CS[(long long)m * ND + j + NHALF] = __float2bfloat16(s);
}

// ------------- chaotic + softmax + sync-variance; emits attn bf16 hi/lo ------
__device__ __forceinline__ float brmax(float v, float* red) {
    int tid = threadIdx.x;
    red[tid] = v; __syncthreads();
    for (int s = 128; s > 0; s >>= 1) {
        if (tid < s) red[tid] = fmaxf(red[tid], red[tid + s]);
        __syncthreads();
    }
    float r = red[0]; __syncthreads();
    return r;
}
__device__ __forceinline__ float brsum(float v, float* red) {
    int tid = threadIdx.x;
    red[tid] = v; __syncthreads();
    for (int s = 128; s > 0; s >>= 1) {
        if (tid < s) red[tid] += red[tid + s];
        __syncthreads();
    }
    float r = red[0]; __syncthreads();
    return r;
}

__global__ __launch_bounds__(256) void softmax_kernel(
    const float* __restrict__ bif_p, const float* __restrict__ pc_p)
{
    __shared__ float red[256];
    const int row = blockIdx.x;
    const float bif = *bif_p;
    const float pc  = *pc_p;
    const float* sc = g_Sc + (long long)row * NS;
    const float* sy = g_Sy + (long long)row * NS;
    __nv_bfloat16* ah = g_Ath + (long long)row * NS;
    __nv_bfloat16* al = g_Atl + (long long)row * NS;

    float c[8];
    float lmax = -1e30f, lsy = 0.0f, lsy2 = 0.0f;
    #pragma unroll
    for (int j = 0; j < 8; j++) {
        int col = threadIdx.x + j * 256;
        float s = sc[col];
        float y = sy[col];
        float t = tanhf(s);
        float v = s + pc * y + bif * t * (1.0f - t);
        c[j] = v;
        lmax = fmaxf(lmax, v);
        lsy  += y;
        lsy2 += y * y;
    }
    float rmax = brmax(lmax, red);

    float lsum = 0.0f;
    #pragma unroll
    for (int j = 0; j < 8; j++) {
        c[j] = expf(c[j] - rmax);
        lsum += c[j];
    }
    float rsum = brsum(lsum, red);
    float inv = 1.0f / rsum;
    #pragma unroll
    for (int j = 0; j < 8; j++) {
        int col = threadIdx.x + j * 256;
        float p = c[j] * inv;
        __nv_bfloat16 hb = __float2bfloat16(p);
        ah[col] = hb;
        al[col] = __float2bfloat16(p - __bfloat162float(hb));
    }

    float tsy  = brsum(lsy,  red);
    float tsy2 = brsum(lsy2, red);
    if (threadIdx.x == 0) {
        float var = (tsy2 - tsy * tsy / (float)NS) / (float)(NS - 1);
        g_rowvar[row] = var;
    }
}

__global__ void finalize_kernel(float* __restrict__ out_scalar)
{
    __shared__ float red[256];
    float s = 0.0f;
    for (int i = threadIdx.x; i < NBS; i += 256) s += g_rowvar[i];
    float tot = brsum(s, red);
    if (threadIdx.x == 0)
        *out_scalar = 0.01f * tot / (float)NBS;
}

// ======================= launch =======================
extern "C" void kernel_launch(void* const* d_in, const int* in_sizes, int n_in,
                              void* d_out, int out_size)
{
    const float* x   = (const float*)d_in[0];
    const float* Wq  = (const float*)d_in[1];
    const float* bq  = (const float*)d_in[2];
    const float* Wk  = (const float*)d_in[3];
    const float* bk  = (const float*)d_in[4];
    const float* Wv  = (const float*)d_in[5];
    const float* bv  = (const float*)d_in[6];
    const float* Wp  = (const float*)d_in[7];
    const float* bp  = (const float*)d_in[8];
    const float* Wo  = (const float*)d_in[9];
    const float* bo  = (const float*)d_in[10];
    const float* bif = (const float*)d_in[11];
    const float* pc  = (const float*)d_in[12];
    float* out = (float*)d_out;

    float *pQ, *pK, *pV, *pP, *pSc, *pSy, *pAV;
    __nv_bfloat16 *pxh, *pxl, *pWqh, *pWql, *pWkh, *pWkl, *pWvh, *pWvl, *pWoh, *pWol, *pWph;
    __nv_bfloat16 *pQh, *pQl, *pKh, *pKl, *pVth, *pVtl, *pCSqh, *pCSkh, *pAth, *pAtl, *pAVh, *pAVl;
    cudaGetSymbolAddress((void**)&pQ,  g_Q);   cudaGetSymbolAddress((void**)&pK,  g_K);
    cudaGetSymbolAddress((void**)&pV,  g_V);   cudaGetSymbolAddress((void**)&pP,  g_P);
    cudaGetSymbolAddress((void**)&pSc, g_Sc);  cudaGetSymbolAddress((void**)&pSy, g_Sy);
    cudaGetSymbolAddress((void**)&pAV, g_AV);
    cudaGetSymbolAddress((void**)&pxh, g_xh);  cudaGetSymbolAddress((void**)&pxl, g_xl);
    cudaGetSymbolAddress((void**)&pWqh, g_Wqh); cudaGetSymbolAddress((void**)&pWql, g_Wql);
    cudaGetSymbolAddress((void**)&pWkh, g_Wkh); cudaGetSymbolAddress((void**)&pWkl, g_Wkl);
    cudaGetSymbolAddress((void**)&pWvh, g_Wvh); cudaGetSymbolAddress((void**)&pWvl, g_Wvl);
    cudaGetSymbolAddress((void**)&pWoh, g_Woh); cudaGetSymbolAddress((void**)&pWol, g_Wol);
    cudaGetSymbolAddress((void**)&pWph, g_Wph);
    cudaGetSymbolAddress((void**)&pQh, g_Qh);  cudaGetSymbolAddress((void**)&pQl, g_Ql);
    cudaGetSymbolAddress((void**)&pKh, g_Kh);  cudaGetSymbolAddress((void**)&pKl, g_Kl);
    cudaGetSymbolAddress((void**)&pVth, g_Vth); cudaGetSymbolAddress((void**)&pVtl, g_Vtl);
    cudaGetSymbolAddress((void**)&pCSqh, g_CSqh); cudaGetSymbolAddress((void**)&pCSkh, g_CSkh);
    cudaGetSymbolAddress((void**)&pAth, g_Ath); cudaGetSymbolAddress((void**)&pAtl, g_Atl);
    cudaGetSymbolAddress((void**)&pAVh, g_AVh); cudaGetSymbolAddress((void**)&pAVl, g_AVl);

    const int SMEM1 = 2 * (2 * TA + 2 * TB);   // 196608
    const int SMEM0 = 2 * (TA + TB);           // 98304
    cudaFuncSetAttribute(mma_gemm_nt<1>, cudaFuncAttributeMaxDynamicSharedMemorySize, SMEM1);
    cudaFuncSetAttribute(mma_gemm_nt<0>, cudaFuncAttributeMaxDynamicSharedMemorySize, SMEM0);

    // ---- input conversions ----
    split_kernel<<<(NBSD + 255) / 256, 256>>>(x, pxh, pxl, NBSD);
    split_kernel<<<(ND * ND + 255) / 256, 256>>>(Wq, pWqh, pWql, ND * ND);
    split_kernel<<<(ND * ND + 255) / 256, 256>>>(Wk, pWkh, pWkl, ND * ND);
    split_kernel<<<(ND * ND + 255) / 256, 256>>>(Wv, pWvh, pWvl, ND * ND);
    split_kernel<<<(ND * ND + 255) / 256, 256>>>(Wo, pWoh, pWol, ND * ND);
    conv_kernel <<<(ND * ND + 255) / 256, 256>>>(Wp, pWph, ND * ND);

    dim3 gp(ND / BN, NBS / BM, 1);        // (4, 64, 1) projections
    dim3 gs(NS / BN, NS / BM, NB);        // (8, 16, 4) scores/sync
    dim3 ga(ND / BN, NS / BM, NB);        // (4, 16, 4) attn@V

    // ---- projections (split precision) ----
    mma_gemm_nt<1><<<gp, 256, SMEM1>>>(pxh, pxl, pWqh, pWql, bq, pQ, ND, ND, 1.0f, 0, 0, 0);
    mma_gemm_nt<1><<<gp, 256, SMEM1>>>(pxh, pxl, pWkh, pWkl, bk, pK, ND, ND, 1.0f, 0, 0, 0);
    mma_gemm_nt<1><<<gp, 256, SMEM1>>>(pxh, pxl, pWvh, pWvl, bv, pV, ND, ND, 1.0f, 0, 0, 0);

    split_kernel<<<(NBSD + 255) / 256, 256>>>(pQ, pQh, pQl, NBSD);
    split_kernel<<<(NBSD + 255) / 256, 256>>>(pK, pKh, pKl, NBSD);
    transpose_split_kernel<<<dim3(NS / 32, ND / 32, NB), dim3(32, 8)>>>(pV, pVth, pVtl);

    // ---- phase features (single-pass bf16) ----
    int pn = NBS * NHALF;
    mma_gemm_nt<0><<<gp, 256, SMEM0>>>(pQh, 0, pWph, 0, bp, pP, ND, ND, 1.0f, 0, 0, 0);
    phase_kernel<<<(pn + 255) / 256, 256>>>(pP, pCSqh);
    mma_gemm_nt<0><<<gp, 256, SMEM0>>>(pKh, 0, pWph, 0, bp, pP, ND, ND, 1.0f, 0, 0, 0);
    phase_kernel<<<(pn + 255) / 256, 256>>>(pP, pCSkh);

    // ---- scores (split) & sync (single-pass) ----
    long long sQK = (long long)NS * ND;
    long long sSS = (long long)NS * NS;
    mma_gemm_nt<1><<<gs, 256, SMEM1>>>(pQh, pQl, pKh, pKl, 0, pSc, NS, ND, 1.0f / 32.0f, sQK, sQK, sSS);
    mma_gemm_nt<0><<<gs, 256, SMEM0>>>(pCSqh, 0, pCSkh, 0, 0, pSy, NS, ND, 1.0f / 512.0f, sQK, sQK, sSS);

    // ---- chaotic + softmax -> attn bf16 hi/lo + per-row sync var ----
    softmax_kernel<<<NBS, 256>>>(bif, pc);

    // ---- av = attn @ V  (NT against transposed V, split) ----
    mma_gemm_nt<1><<<ga, 256, SMEM1>>>(pAth, pAtl, pVth, pVtl, 0, pAV, ND, NS, 1.0f, sSS, sQK, sQK);

    split_kernel<<<(NBSD + 255) / 256, 256>>>(pAV, pAVh, pAVl, NBSD);

    // ---- out = av @ Wo^T + bo -> d_out ----
    mma_gemm_nt<1><<<gp, 256, SMEM1>>>(pAVh, pAVl, pWoh, pWol, bo, out, ND, ND, 1.0f, 0, 0, 0);

    // ---- sync_loss scalar ----
    finalize_kernel<<<1, 256>>>(out + (out_size - 1));
}

// round 5
// speedup vs baseline: 4.2200x; 1.0536x over previous
#include <cuda_runtime.h>
#include <cuda_bf16.h>
#include <math.h>
#include <stdint.h>

// Problem constants
#define NB 4
#define NS 2048
#define ND 1024
#define NHALF 512
#define NBS (NB*NS)            // 8192
#define NBSD (NB*NS*ND)        // 8388608
#define NSS 16777216           // NB*NS*NS

// ---------------- scratch (static device globals; no allocation) -------------
__device__ float g_V[NBSD];
__device__ float g_P[NBSD];
__device__ float g_Sc[NSS];     // scores fp32
__device__ float g_Sy[NSS];     // sync fp32
__device__ float g_rowvar[NBS];

__device__ __nv_bfloat16 g_xh[NBSD],  g_xl[NBSD];
__device__ __nv_bfloat16 g_Wqh[ND*ND], g_Wql[ND*ND];
__device__ __nv_bfloat16 g_Wkh[ND*ND], g_Wkl[ND*ND];
__device__ __nv_bfloat16 g_Wvh[ND*ND], g_Wvl[ND*ND];
__device__ __nv_bfloat16 g_Woh[ND*ND], g_Wol[ND*ND];
__device__ __nv_bfloat16 g_Wph[ND*ND];
__device__ __nv_bfloat16 g_Qh[NBSD], g_Ql[NBSD];
__device__ __nv_bfloat16 g_Kh[NBSD], g_Kl[NBSD];
__device__ __nv_bfloat16 g_Vth[NBSD], g_Vtl[NBSD];
__device__ __nv_bfloat16 g_CSqh[NBSD], g_CSkh[NBSD];
__device__ __nv_bfloat16 g_Ath[NSS], g_Atl[NSS];
__device__ __nv_bfloat16 g_AVh[NBSD], g_AVl[NBSD];

// ======================= PTX helpers (all sm_80-baseline) =======================
__device__ __forceinline__ uint32_t s2u(const void* p) {
    uint32_t a;
    asm("{ .reg .u64 t; cvta.to.shared.u64 t, %1; cvt.u32.u64 %0, t; }" : "=r"(a) : "l"(p));
    return a;
}
__device__ __forceinline__ void cp16(uint32_t dst, const void* src) {
    asm volatile("cp.async.cg.shared.global [%0], [%1], 16;" :: "r"(dst), "l"(src) : "memory");
}
__device__ __forceinline__ void cp_commit() {
    asm volatile("cp.async.commit_group;" ::: "memory");
}
__device__ __forceinline__ void cp_wait1() {
    asm volatile("cp.async.wait_group 1;" ::: "memory");
}
__device__ __forceinline__ void ldsm4(uint32_t& r0, uint32_t& r1, uint32_t& r2, uint32_t& r3,
                                      uint32_t addr) {
    asm volatile("ldmatrix.sync.aligned.m8n8.x4.shared.b16 {%0,%1,%2,%3}, [%4];"
                 : "=r"(r0), "=r"(r1), "=r"(r2), "=r"(r3) : "r"(addr));
}
__device__ __forceinline__ void mma16816(float* c, const uint32_t* a, const uint32_t* b) {
    asm volatile(
        "mma.sync.aligned.m16n8k16.row.col.f32.bf16.bf16.f32 "
        "{%0,%1,%2,%3}, {%4,%5,%6,%7}, {%8,%9}, {%0,%1,%2,%3};"
        : "+f"(c[0]), "+f"(c[1]), "+f"(c[2]), "+f"(c[3])
        : "r"(a[0]), "r"(a[1]), "r"(a[2]), "r"(a[3]), "r"(b[0]), "r"(b[1]));
}
__device__ __forceinline__ __nv_bfloat162 split_pair(float v0, float v1,
                                                     __nv_bfloat162& lo) {
    __nv_bfloat16 h0 = __float2bfloat16(v0), h1 = __float2bfloat16(v1);
    lo = __nv_bfloat162(__float2bfloat16(v0 - __bfloat162float(h0)),
                        __float2bfloat16(v1 - __bfloat162float(h1)));
    return __nv_bfloat162(h0, h1);
}

// ======================= mma.sync GEMM NT =======================
// C = alpha * (Ah+Al)(Bh+Bl)^T (+bias). CTA tile 128x256, K-chunk 64, SW128,
// 8 warps (2m x 4n), warp tile 64x64, 2-stage cp.async pipeline.
// OUTM: 0 = fp32 output, 1 = split bf16 hi/lo output.
#define BM 128
#define BN 256
#define TA 16384    // 128 rows * 128B
#define TB 32768    // 256 rows * 128B

__device__ __forceinline__ void ld_tile(uint32_t dst, const __nv_bfloat16* g,
                                        int ldk, int rows, int tid) {
    const char* base = (const char*)g;
    int tot = rows * 8;
    for (int idx = tid; idx < tot; idx += 256) {
        int r = idx >> 3, c = idx & 7;
        uint32_t off = (uint32_t)(r * 128 + c * 16);
        uint32_t sw = off ^ ((off >> 3) & 0x70);
        cp16(dst + sw, base + (long long)r * ldk * 2 + c * 16);
    }
}

template<int SPLIT>
__device__ __forceinline__ void load_chunk(uint32_t sbase, int s,
    const __nv_bfloat16* pAh, const __nv_bfloat16* pAl,
    const __nv_bfloat16* pBh, const __nv_bfloat16* pBl,
    int Kd, int k0, int tid)
{
    const int STG = SPLIT ? (2 * TA + 2 * TB) : (TA + TB);
    uint32_t sb = sbase + s * STG;
    ld_tile(sb, pAh + k0, Kd, BM, tid);
    if (SPLIT) ld_tile(sb + TA, pAl + k0, Kd, BM, tid);
    ld_tile(sb + (SPLIT ? 2 * TA : TA), pBh + k0, Kd, BN, tid);
    if (SPLIT) ld_tile(sb + 2 * TA + TB, pBl + k0, Kd, BN, tid);
}

template<int SPLIT, int OUTM>
__global__ __launch_bounds__(256, 1)
void mma_gemm_nt(const __nv_bfloat16* __restrict__ Ah, const __nv_bfloat16* __restrict__ Al,
                 const __nv_bfloat16* __restrict__ Bh, const __nv_bfloat16* __restrict__ Bl,
                 const float* __restrict__ bias, float* __restrict__ C,
                 __nv_bfloat16* __restrict__ Ch, __nv_bfloat16* __restrict__ Cl,
                 int N, int Kd, float alpha,
                 long long sA, long long sB, long long sC)
{
    extern __shared__ __align__(128) char smem[];
    const int STG = SPLIT ? (2 * TA + 2 * TB) : (TA + TB);
    const int tid = threadIdx.x;
    const int wid = tid >> 5, lane = tid & 31;
    const int wm = wid >> 2, wn = wid & 3;
    const uint32_t sbase = s2u(smem);

    const int m0 = blockIdx.y * BM, n0 = blockIdx.x * BN;
    const long long bz = blockIdx.z;
    const __nv_bfloat16* pAh = Ah + bz * sA + (long long)m0 * Kd;
    const __nv_bfloat16* pBh = Bh + bz * sB + (long long)n0 * Kd;
    const __nv_bfloat16* pAl = SPLIT ? Al + bz * sA + (long long)m0 * Kd : (const __nv_bfloat16*)0;
    const __nv_bfloat16* pBl = SPLIT ? Bl + bz * sB + (long long)n0 * Kd : (const __nv_bfloat16*)0;

    // per-lane swizzled ldmatrix bases; k-advance is XORed (swizzle field!)
    const int qa = lane >> 3, rl = lane & 7;
    const int rowA = wm * 64 + (qa & 1) * 8 + rl;
    uint32_t offA = (uint32_t)(rowA * 128 + (qa >> 1) * 16);
    const uint32_t swA = offA ^ ((offA >> 3) & 0x70);
    const int rowB = wn * 64 + (qa >> 1) * 8 + rl;
    uint32_t offB = (uint32_t)(rowB * 128 + (qa & 1) * 16);
    const uint32_t swB = offB ^ ((offB >> 3) & 0x70);

    float acc[4][8][4];
    #pragma unroll
    for (int i = 0; i < 4; i++)
        #pragma unroll
        for (int j = 0; j < 8; j++)
            #pragma unroll
            for (int r = 0; r < 4; r++) acc[i][j][r] = 0.0f;

    const int nk = Kd / 64;
    load_chunk<SPLIT>(sbase, 0, pAh, pAl, pBh, pBl, Kd, 0, tid);  cp_commit();
    load_chunk<SPLIT>(sbase, 1, pAh, pAl, pBh, pBl, Kd, 64, tid); cp_commit();

    for (int i = 0; i < nk; i++) {
        int s = i & 1;
        cp_wait1();
        __syncthreads();

        uint32_t sb = sbase + s * STG;
        uint32_t aH = sb;
        uint32_t aL = sb + TA;
        uint32_t bH = sb + (SPLIT ? 2 * TA : TA);
        uint32_t bL = bH + TB;

        #pragma unroll
        for (int ks = 0; ks < 4; ks++) {
            uint32_t kb = ks * 32;
            uint32_t ah[4][4], bh[8][2];
            #pragma unroll
            for (int mt = 0; mt < 4; mt++)
                ldsm4(ah[mt][0], ah[mt][1], ah[mt][2], ah[mt][3],
                      aH + ((swA ^ kb) + mt * 2048));
            #pragma unroll
            for (int g = 0; g < 4; g++)
                ldsm4(bh[2*g][0], bh[2*g][1], bh[2*g+1][0], bh[2*g+1][1],
                      bH + ((swB ^ kb) + g * 2048));
            if (SPLIT) {
                uint32_t bl[8][2];
                #pragma unroll
                for (int g = 0; g < 4; g++)
                    ldsm4(bl[2*g][0], bl[2*g][1], bl[2*g+1][0], bl[2*g+1][1],
                          bL + ((swB ^ kb) + g * 2048));
                #pragma unroll
                for (int mt = 0; mt < 4; mt++)
                    #pragma unroll
                    for (int nt = 0; nt < 8; nt++) {
                        mma16816(acc[mt][nt], ah[mt], bh[nt]);
                        mma16816(acc[mt][nt], ah[mt], bl[nt]);
                    }
                uint32_t al[4][4];
                #pragma unroll
                for (int mt = 0; mt < 4; mt++)
                    ldsm4(al[mt][0], al[mt][1], al[mt][2], al[mt][3],
                          aL + ((swA ^ kb) + mt * 2048));
                #pragma unroll
                for (int mt = 0; mt < 4; mt++)
                    #pragma unroll
                    for (int nt = 0; nt < 8; nt++)
                        mma16816(acc[mt][nt], al[mt], bh[nt]);
            } else {
                #pragma unroll
                for (int mt = 0; mt < 4; mt++)
                    #pragma unroll
                    for (int nt = 0; nt < 8; nt++)
                        mma16816(acc[mt][nt], ah[mt], bh[nt]);
            }
        }

        __syncthreads();
        if (i + 2 < nk)
            load_chunk<SPLIT>(sbase, s, pAh, pAl, pBh, pBl, Kd, (i + 2) * 64, tid);
        cp_commit();
    }

    // epilogue
    const int t4 = lane >> 2, t2 = (lane & 3) * 2;
    #pragma unroll
    for (int mt = 0; mt < 4; mt++) {
        int r0 = m0 + wm * 64 + mt * 16 + t4;
        #pragma unroll
        for (int nt = 0; nt < 8; nt++) {
            int col = n0 + wn * 64 + nt * 8 + t2;
            float b0 = 0.0f, b1 = 0.0f;
            if (bias) { b0 = bias[col]; b1 = bias[col + 1]; }
            float v00 = alpha * acc[mt][nt][0] + b0, v01 = alpha * acc[mt][nt][1] + b1;
            float v10 = alpha * acc[mt][nt][2] + b0, v11 = alpha * acc[mt][nt][3] + b1;
            if (OUTM == 0) {
                float* pC = C + bz * sC;
                *(float2*)&pC[(long long)r0 * N + col]       = make_float2(v00, v01);
                *(float2*)&pC[(long long)(r0 + 8) * N + col] = make_float2(v10, v11);
            } else {
                __nv_bfloat16* pH = Ch + bz * sC;
                __nv_bfloat16* pL = Cl + bz * sC;
                __nv_bfloat162 l0, l1;
                __nv_bfloat162 h0 = split_pair(v00, v01, l0);
                __nv_bfloat162 h1 = split_pair(v10, v11, l1);
                *(__nv_bfloat162*)&pH[(long long)r0 * N + col]       = h0;
                *(__nv_bfloat162*)&pL[(long long)r0 * N + col]       = l0;
                *(__nv_bfloat162*)&pH[(long long)(r0 + 8) * N + col] = h1;
                *(__nv_bfloat162*)&pL[(long long)(r0 + 8) * N + col] = l1;
            }
        }
    }
}

// ======================= elementwise kernels =======================
// vectorized split: float4 in -> 2x bf16x2 out (n must be /4)
__global__ void split4_kernel(const float* __restrict__ in,
                              __nv_bfloat16* __restrict__ h, __nv_bfloat16* __restrict__ l, int n4)
{
    int i = blockIdx.x * blockDim.x + threadIdx.x;
    if (i >= n4) return;
    float4 f = ((const float4*)in)[i];
    __nv_bfloat162 l0, l1;
    __nv_bfloat162 h0 = split_pair(f.x, f.y, l0);
    __nv_bfloat162 h1 = split_pair(f.z, f.w, l1);
    ((__nv_bfloat162*)h)[i * 2]     = h0;
    ((__nv_bfloat162*)h)[i * 2 + 1] = h1;
    ((__nv_bfloat162*)l)[i * 2]     = l0;
    ((__nv_bfloat162*)l)[i * 2 + 1] = l1;
}

__global__ void conv4_kernel(const float* __restrict__ in, __nv_bfloat16* __restrict__ h, int n4)
{
    int i = blockIdx.x * blockDim.x + threadIdx.x;
    if (i >= n4) return;
    float4 f = ((const float4*)in)[i];
    ((__nv_bfloat162*)h)[i * 2]     = __nv_bfloat162(__float2bfloat16(f.x), __float2bfloat16(f.y));
    ((__nv_bfloat162*)h)[i * 2 + 1] = __nv_bfloat162(__float2bfloat16(f.z), __float2bfloat16(f.w));
}

// transpose V[b][s][d] -> Vt[b][d][s], split into bf16 hi/lo
__global__ void transpose_split_kernel(const float* __restrict__ V,
                                       __nv_bfloat16* __restrict__ Th, __nv_bfloat16* __restrict__ Tl)
{
    __shared__ float t[32][33];
    int b = blockIdx.z;
    int s0 = blockIdx.x * 32, d0 = blockIdx.y * 32;
    int tx = threadIdx.x, ty = threadIdx.y;
    #pragma unroll
    for (int yy = 0; yy < 4; yy++) {
        int s = s0 + ty + 8 * yy;
        t[ty + 8 * yy][tx] = V[((long long)b * NS + s) * ND + d0 + tx];
    }
    __syncthreads();
    #pragma unroll
    for (int yy = 0; yy < 4; yy++) {
        int d = d0 + ty + 8 * yy;
        int s = s0 + tx;
        float f = t[tx][ty + 8 * yy];
        __nv_bfloat16 hb = __float2bfloat16(f);
        long long o = ((long long)b * ND + d) * NS + s;
        Th[o] = hb;
        Tl[o] = __float2bfloat16(f - __bfloat162float(hb));
    }
}

// phase features: cos/sin of atan2 -> bf16 [cos | sin]
__global__ void phase_kernel(const float* __restrict__ P, __nv_bfloat16* __restrict__ CS)
{
    int i = blockIdx.x * blockDim.x + threadIdx.x;
    if (i >= NBS * NHALF) return;
    int m = i / NHALF;
    int j = i - m * NHALF;
    float re = P[(long long)m * ND + j];
    float im = P[(long long)m * ND + j + NHALF];
    float r2 = re * re + im * im;
    float c, s;
    if (r2 > 0.0f) {
        float inv = rsqrtf(r2);
        c = re * inv; s = im * inv;
    } else { c = 1.0f; s = 0.0f; }
    CS[(long long)m * ND + j]         = __float2bfloat16(c);
    CS[(long long)m * ND + j + NHALF] = __float2bfloat16(s);
}

// ------------- chaotic + softmax + sync-variance; emits attn bf16 hi/lo ------
__device__ __forceinline__ float brmax(float v, float* red) {
    int tid = threadIdx.x;
    red[tid] = v; __syncthreads();
    for (int s = 128; s > 0; s >>= 1) {
        if (tid < s) red[tid] = fmaxf(red[tid], red[tid + s]);
        __syncthreads();
    }
    float r = red[0]; __syncthreads();
    return r;
}
__device__ __forceinline__ float brsum(float v, float* red) {
    int tid = threadIdx.x;
    red[tid] = v; __syncthreads();
    for (int s = 128; s > 0; s >>= 1) {
        if (tid < s) red[tid] += red[tid + s];
        __syncthreads();
    }
    float r = red[0]; __syncthreads();
    return r;
}

__global__ __launch_bounds__(256) void softmax_kernel(
    const float* __restrict__ bif_p, const float* __restrict__ pc_p)
{
    __shared__ float red[256];
    const int row = blockIdx.x;
    const float bif = *bif_p;
    const float pc  = *pc_p;
    const float4* sc4 = (const float4*)(g_Sc + (long long)row * NS);
    const float4* sy4 = (const float4*)(g_Sy + (long long)row * NS);
    __nv_bfloat162* ah2 = (__nv_bfloat162*)(g_Ath + (long long)row * NS);
    __nv_bfloat162* al2 = (__nv_bfloat162*)(g_Atl + (long long)row * NS);

    float c[2][4];
    float lmax = -1e30f, lsy = 0.0f, lsy2 = 0.0f;
    #pragma unroll
    for (int j = 0; j < 2; j++) {
        int idx = threadIdx.x + j * 256;       // float4 index, 512 per row
        float4 s4 = sc4[idx];
        float4 y4 = sy4[idx];
        float sv[4] = { s4.x, s4.y, s4.z, s4.w };
        float yv[4] = { y4.x, y4.y, y4.z, y4.w };
        #pragma unroll
        for (int e = 0; e < 4; e++) {
            float t = tanhf(sv[e]);
            float v = sv[e] + pc * yv[e] + bif * t * (1.0f - t);
            c[j][e] = v;
            lmax = fmaxf(lmax, v);
            lsy  += yv[e];
            lsy2 += yv[e] * yv[e];
        }
    }
    float rmax = brmax(lmax, red);

    float lsum = 0.0f;
    #pragma unroll
    for (int j = 0; j < 2; j++)
        #pragma unroll
        for (int e = 0; e < 4; e++) {
            c[j][e] = expf(c[j][e] - rmax);
            lsum += c[j][e];
        }
    float rsum = brsum(lsum, red);
    float inv = 1.0f / rsum;
    #pragma unroll
    for (int j = 0; j < 2; j++) {
        int idx = threadIdx.x + j * 256;
        __nv_bfloat162 l0, l1;
        __nv_bfloat162 h0 = split_pair(c[j][0] * inv, c[j][1] * inv, l0);
        __nv_bfloat162 h1 = split_pair(c[j][2] * inv, c[j][3] * inv, l1);
        ah2[idx * 2]     = h0;
        ah2[idx * 2 + 1] = h1;
        al2[idx * 2]     = l0;
        al2[idx * 2 + 1] = l1;
    }

    float tsy  = brsum(lsy,  red);
    float tsy2 = brsum(lsy2, red);
    if (threadIdx.x == 0) {
        float var = (tsy2 - tsy * tsy / (float)NS) / (float)(NS - 1);
        g_rowvar[row] = var;
    }
}

__global__ void finalize_kernel(float* __restrict__ out_scalar)
{
    __shared__ float red[256];
    float s = 0.0f;
    for (int i = threadIdx.x; i < NBS; i += 256) s += g_rowvar[i];
    float tot = brsum(s, red);
    if (threadIdx.x == 0)
        *out_scalar = 0.01f * tot / (float)NBS;
}

// ======================= launch =======================
extern "C" void kernel_launch(void* const* d_in, const int* in_sizes, int n_in,
                              void* d_out, int out_size)
{
    const float* x   = (const float*)d_in[0];
    const float* Wq  = (const float*)d_in[1];
    const float* bq  = (const float*)d_in[2];
    const float* Wk  = (const float*)d_in[3];
    const float* bk  = (const float*)d_in[4];
    const float* Wv  = (const float*)d_in[5];
    const float* bv  = (const float*)d_in[6];
    const float* Wp  = (const float*)d_in[7];
    const float* bp  = (const float*)d_in[8];
    const float* Wo  = (const float*)d_in[9];
    const float* bo  = (const float*)d_in[10];
    const float* bif = (const float*)d_in[11];
    const float* pc  = (const float*)d_in[12];
    float* out = (float*)d_out;

    float *pV, *pP, *pSc, *pSy;
    __nv_bfloat16 *pxh, *pxl, *pWqh, *pWql, *pWkh, *pWkl, *pWvh, *pWvl, *pWoh, *pWol, *pWph;
    __nv_bfloat16 *pQh, *pQl, *pKh, *pKl, *pVth, *pVtl, *pCSqh, *pCSkh, *pAth, *pAtl, *pAVh, *pAVl;
    cudaGetSymbolAddress((void**)&pV,  g_V);   cudaGetSymbolAddress((void**)&pP,  g_P);
    cudaGetSymbolAddress((void**)&pSc, g_Sc);  cudaGetSymbolAddress((void**)&pSy, g_Sy);
    cudaGetSymbolAddress((void**)&pxh, g_xh);  cudaGetSymbolAddress((void**)&pxl, g_xl);
    cudaGetSymbolAddress((void**)&pWqh, g_Wqh); cudaGetSymbolAddress((void**)&pWql, g_Wql);
    cudaGetSymbolAddress((void**)&pWkh, g_Wkh); cudaGetSymbolAddress((void**)&pWkl, g_Wkl);
    cudaGetSymbolAddress((void**)&pWvh, g_Wvh); cudaGetSymbolAddress((void**)&pWvl, g_Wvl);
    cudaGetSymbolAddress((void**)&pWoh, g_Woh); cudaGetSymbolAddress((void**)&pWol, g_Wol);
    cudaGetSymbolAddress((void**)&pWph, g_Wph);
    cudaGetSymbolAddress((void**)&pQh, g_Qh);  cudaGetSymbolAddress((void**)&pQl, g_Ql);
    cudaGetSymbolAddress((void**)&pKh, g_Kh);  cudaGetSymbolAddress((void**)&pKl, g_Kl);
    cudaGetSymbolAddress((void**)&pVth, g_Vth); cudaGetSymbolAddress((void**)&pVtl, g_Vtl);
    cudaGetSymbolAddress((void**)&pCSqh, g_CSqh); cudaGetSymbolAddress((void**)&pCSkh, g_CSkh);
    cudaGetSymbolAddress((void**)&pAth, g_Ath); cudaGetSymbolAddress((void**)&pAtl, g_Atl);
    cudaGetSymbolAddress((void**)&pAVh, g_AVh); cudaGetSymbolAddress((void**)&pAVl, g_AVl);

    const int SMEM1 = 2 * (2 * TA + 2 * TB);   // 196608
    const int SMEM0 = 2 * (TA + TB);           // 98304
    cudaFuncSetAttribute(mma_gemm_nt<1,0>, cudaFuncAttributeMaxDynamicSharedMemorySize, SMEM1);
    cudaFuncSetAttribute(mma_gemm_nt<1,1>, cudaFuncAttributeMaxDynamicSharedMemorySize, SMEM1);
    cudaFuncSetAttribute(mma_gemm_nt<0,0>, cudaFuncAttributeMaxDynamicSharedMemorySize, SMEM0);

    // ---- input conversions (vectorized) ----
    split4_kernel<<<(NBSD/4 + 255) / 256, 256>>>(x, pxh, pxl, NBSD/4);
    split4_kernel<<<(ND*ND/4 + 255) / 256, 256>>>(Wq, pWqh, pWql, ND*ND/4);
    split4_kernel<<<(ND*ND/4 + 255) / 256, 256>>>(Wk, pWkh, pWkl, ND*ND/4);
    split4_kernel<<<(ND*ND/4 + 255) / 256, 256>>>(Wv, pWvh, pWvl, ND*ND/4);
    split4_kernel<<<(ND*ND/4 + 255) / 256, 256>>>(Wo, pWoh, pWol, ND*ND/4);
    conv4_kernel <<<(ND*ND/4 + 255) / 256, 256>>>(Wp, pWph, ND*ND/4);

    dim3 gp(ND / BN, NBS / BM, 1);        // (4, 64, 1) projections
    dim3 gs(NS / BN, NS / BM, NB);        // (8, 16, 4) scores/sync
    dim3 ga(ND / BN, NS / BM, NB);        // (4, 16, 4) attn@V

    // ---- projections: Q,K split straight to bf16 hi/lo; V to fp32 ----
    mma_gemm_nt<1,1><<<gp, 256, SMEM1>>>(pxh, pxl, pWqh, pWql, bq, 0, pQh, pQl, ND, ND, 1.0f, 0, 0, 0);
    mma_gemm_nt<1,1><<<gp, 256, SMEM1>>>(pxh, pxl, pWkh, pWkl, bk, 0, pKh, pKl, ND, ND, 1.0f, 0, 0, 0);
    mma_gemm_nt<1,0><<<gp, 256, SMEM1>>>(pxh, pxl, pWvh, pWvl, bv, pV, 0, 0, ND, ND, 1.0f, 0, 0, 0);

    transpose_split_kernel<<<dim3(NS / 32, ND / 32, NB), dim3(32, 8)>>>(pV, pVth, pVtl);

    // ---- phase features (single-pass bf16) ----
    int pn = NBS * NHALF;
    mma_gemm_nt<0,0><<<gp, 256, SMEM0>>>(pQh, 0, pWph, 0, bp, pP, 0, 0, ND, ND, 1.0f, 0, 0, 0);
    phase_kernel<<<(pn + 255) / 256, 256>>>(pP, pCSqh);
    mma_gemm_nt<0,0><<<gp, 256, SMEM0>>>(pKh, 0, pWph, 0, bp, pP, 0, 0, ND, ND, 1.0f, 0, 0, 0);
    phase_kernel<<<(pn + 255) / 256, 256>>>(pP, pCSkh);

    // ---- scores (split) & sync (single-pass) ----
    long long sQK = (long long)NS * ND;
    long long sSS = (long long)NS * NS;
    mma_gemm_nt<1,0><<<gs, 256, SMEM1>>>(pQh, pQl, pKh, pKl, 0, pSc, 0, 0, NS, ND, 1.0f / 32.0f, sQK, sQK, sSS);
    mma_gemm_nt<0,0><<<gs, 256, SMEM0>>>(pCSqh, 0, pCSkh, 0, 0, pSy, 0, 0, NS, ND, 1.0f / 512.0f, sQK, sQK, sSS);

    // ---- chaotic + softmax -> attn bf16 hi/lo + per-row sync var ----
    softmax_kernel<<<NBS, 256>>>(bif, pc);

    // ---- av = attn @ V^T (split) -> bf16 hi/lo directly ----
    mma_gemm_nt<1,1><<<ga, 256, SMEM1>>>(pAth, pAtl, pVth, pVtl, 0, 0, pAVh, pAVl, ND, NS, 1.0f, sSS, sQK, sQK);

    // ---- out = av @ Wo^T + bo -> d_out ----
    mma_gemm_nt<1,0><<<gp, 256, SMEM1>>>(pAVh, pAVl, pWoh, pWol, bo, out, 0, 0, ND, ND, 1.0f, 0, 0, 0);

    // ---- sync_loss scalar ----
    finalize_kernel<<<1, 256>>>(out + (out_size - 1));
}